// round 4
// baseline (speedup 1.0000x reference)
#include <cuda_runtime.h>
#include <mma.h>
#include <cstdint>
using namespace nvcuda;

#define Nn 50000
#define Ee 800000
#define Hh 4
#define Dd 128
#define HDd 512
#define Ll 4
#define MPAD 50048   // 391 * 128, pads GEMM M-tiles so epilogue stores are unguarded

// ---------------- scratch (static device memory; no allocations) ----------------
__device__ __align__(16) float g_feat[(size_t)MPAD * HDd];
__device__ __align__(16) float g_res [(size_t)MPAD * HDd];
__device__ __align__(16) float g_el[Nn * Hh];
__device__ __align__(16) float g_er[Nn * Hh];
__device__ __align__(16) float g_m4 [Nn * Hh];
__device__ __align__(16) float g_iz4[Nn * Hh];
__device__ __align__(16) float g_y [(size_t)MPAD * Dd];
__device__ __align__(16) float g_xA[(size_t)Nn * Dd];
__device__ __align__(16) float g_xB[(size_t)Nn * Dd];
__device__ int g_deg[Nn];
__device__ int g_rowptr[Nn + 1];
__device__ int g_cursor[Nn];
__device__ int g_csrsrc[Ee];

// ---------------- CSR build ----------------
__global__ void k_zero_deg() {
    int i = blockIdx.x * blockDim.x + threadIdx.x;
    if (i < Nn) g_deg[i] = 0;
}

__global__ void k_count(const int* __restrict__ dst) {
    int i = blockIdx.x * blockDim.x + threadIdx.x;
    if (i < Ee) atomicAdd(&g_deg[dst[i]], 1);
}

// single-block exclusive scan over g_deg -> g_rowptr (+ cursor init fused)
__global__ void k_scan() {
    __shared__ int sh[1024];
    __shared__ int carry;
    int t = threadIdx.x;
    if (t == 0) { carry = 0; g_rowptr[0] = 0; }
    __syncthreads();
    for (int base = 0; base < Nn; base += 1024) {
        int i = base + t;
        int v = (i < Nn) ? g_deg[i] : 0;
        sh[t] = v;
        __syncthreads();
        #pragma unroll
        for (int off = 1; off < 1024; off <<= 1) {
            int tv = (t >= off) ? sh[t - off] : 0;
            __syncthreads();
            sh[t] += tv;
            __syncthreads();
        }
        int incl = sh[t];
        int c = carry;
        __syncthreads();
        if (i < Nn) {
            g_rowptr[i + 1] = c + incl;
            g_cursor[i] = c + incl - v;
        }
        if (t == 1023) carry = c + incl;
        __syncthreads();
    }
}

__global__ void k_fill(const int* __restrict__ src, const int* __restrict__ dst) {
    int i = blockIdx.x * blockDim.x + threadIdx.x;
    if (i < Ee) {
        int p = atomicAdd(&g_cursor[dst[i]], 1);
        g_csrsrc[p] = src[i];
    }
}

// ---------------- cp.async helper ----------------
__device__ __forceinline__ void cp16(uint32_t dst, const void* src, bool pred) {
    int sz = pred ? 16 : 0;
    asm volatile("cp.async.cg.shared.global [%0], [%1], 16, %2;\n"
                 :: "r"(dst), "l"(src), "r"(sz));
}

// ---------------- tf32 tensor-core GEMM, 4-stage cp.async, fused dual output ----------
// CTA 128x128 C tile, BK=8, 8 warps (2m x 4n), warp tile 64x32 (4x2 wmma m16n16k8).
// Dual-output: blockIdx.x < tilesPerHalf -> B0/C0 else B1/C1 (same A).
// Single __syncthreads per K-step. C rows written unguarded -> C padded to MPAD.
__global__ __launch_bounds__(256) void gemm_tc(
    const float* __restrict__ A,
    const float* __restrict__ B0, const float* __restrict__ B1,
    float* __restrict__ C0, float* __restrict__ C1,
    int M, int N, int K, int tilesPerHalf)
{
    __shared__ float As[4][128][12];   // [m][k] ld 12
    __shared__ float Bs[4][8][132];    // [k][n] ld 132

    const int tid = threadIdx.x;
    const int warp = tid >> 5;
    const int wm = warp & 1, wn = warp >> 1;
    const int row0 = blockIdx.y * 128;

    int bx = blockIdx.x;
    const float* B = B0;
    float* C = C0;
    if (bx >= tilesPerHalf) { bx -= tilesPerHalf; B = B1; C = C1; }
    const int col0 = bx * 128;

    wmma::fragment<wmma::accumulator, 16, 16, 8, float> acc[4][2];
    #pragma unroll
    for (int i = 0; i < 4; i++)
        #pragma unroll
        for (int j = 0; j < 2; j++)
            wmma::fill_fragment(acc[i][j], 0.0f);

    const int KT = K >> 3;

    // stage one BK=8 slab: A 128x8 (1 float4/thread... 2 per: 1024 floats), B 8x128
    auto stage = [&](int buf, int k0) {
        {
            int r = tid >> 1, q = tid & 1;          // 128 rows x 2 float4
            int gm = row0 + r;
            const float* srcp = A + (size_t)gm * K + k0 + q * 4;
            uint32_t d = (uint32_t)__cvta_generic_to_shared(&As[buf][r][q * 4]);
            cp16(d, srcp, gm < M);
        }
        {
            int r = tid >> 5, nq = tid & 31;        // 8 rows x 32 float4
            const float* srcp = B + (size_t)(k0 + r) * N + col0 + nq * 4;
            uint32_t d = (uint32_t)__cvta_generic_to_shared(&Bs[buf][r][nq * 4]);
            cp16(d, srcp, true);
        }
        asm volatile("cp.async.commit_group;");
    };

    stage(0, 0);
    stage(1, 8);
    stage(2, 16);

    for (int kt = 0; kt < KT; kt++) {
        if (kt + 3 < KT) asm volatile("cp.async.wait_group 2;");
        else             asm volatile("cp.async.wait_group 0;");
        __syncthreads();

        int buf = kt & 3;
        wmma::fragment<wmma::matrix_a, 16, 16, 8, wmma::precision::tf32, wmma::row_major> a[4];
        wmma::fragment<wmma::matrix_b, 16, 16, 8, wmma::precision::tf32, wmma::row_major> b[2];
        #pragma unroll
        for (int i = 0; i < 4; i++) {
            wmma::load_matrix_sync(a[i], &As[buf][wm * 64 + i * 16][0], 12);
            #pragma unroll
            for (int t = 0; t < a[i].num_elements; t++)
                a[i].x[t] = wmma::__float_to_tf32(a[i].x[t]);
        }
        #pragma unroll
        for (int j = 0; j < 2; j++) {
            wmma::load_matrix_sync(b[j], &Bs[buf][0][wn * 32 + j * 16], 132);
            #pragma unroll
            for (int t = 0; t < b[j].num_elements; t++)
                b[j].x[t] = wmma::__float_to_tf32(b[j].x[t]);
        }
        #pragma unroll
        for (int i = 0; i < 4; i++)
            #pragma unroll
            for (int j = 0; j < 2; j++)
                wmma::mma_sync(acc[i][j], a[i], b[j], acc[i][j]);

        if (kt + 3 < KT) stage((kt + 3) & 3, (kt + 3) << 3);
    }

    #pragma unroll
    for (int i = 0; i < 4; i++)
        #pragma unroll
        for (int j = 0; j < 2; j++)
            wmma::store_matrix_sync(
                C + (size_t)(row0 + wm * 64 + i * 16) * N + col0 + wn * 32 + j * 16,
                acc[i][j], N, wmma::mem_row_major);
}

// ---------------- attention coefficients: el/er = feat . attn ----------------
__global__ __launch_bounds__(128) void k_attn(
    const float* __restrict__ feat,
    const float* __restrict__ al, const float* __restrict__ ar)
{
    int n = blockIdx.x;
    int h = threadIdx.x >> 5, lane = threadIdx.x & 31;
    float4 f = ((const float4*)(feat + (size_t)n * HDd + h * Dd))[lane];
    float4 a = ((const float4*)(al + h * Dd))[lane];
    float4 b = ((const float4*)(ar + h * Dd))[lane];
    float sl = f.x * a.x + f.y * a.y + f.z * a.z + f.w * a.w;
    float sr = f.x * b.x + f.y * b.y + f.z * b.z + f.w * b.w;
    #pragma unroll
    for (int o = 16; o; o >>= 1) {
        sl += __shfl_xor_sync(0xffffffffu, sl, o);
        sr += __shfl_xor_sync(0xffffffffu, sr, o);
    }
    if (lane == 0) {
        g_el[n * Hh + h] = sl;
        g_er[n * Hh + h] = sr;
    }
}

// ---------------- pass A: per-(node,head) softmax max & denominator ----------------
__global__ __launch_bounds__(128) void k_mz() {
    int n = blockIdx.x * 4 + (threadIdx.x >> 5);
    int lane = threadIdx.x & 31;
    if (n >= Nn) return;
    int beg = g_rowptr[n], end = g_rowptr[n + 1];
    float4 er = *(const float4*)(g_er + n * 4);

    float m0 = -1e30f, m1 = -1e30f, m2 = -1e30f, m3 = -1e30f;
    float z0 = 0.f, z1 = 0.f, z2 = 0.f, z3 = 0.f;

    for (int e = beg + lane; e < end; e += 32) {
        int s = g_csrsrc[e];
        float4 el = *(const float4*)(g_el + s * 4);
        float v0 = el.x + er.x; v0 = v0 > 0.f ? v0 : 0.2f * v0;
        float v1 = el.y + er.y; v1 = v1 > 0.f ? v1 : 0.2f * v1;
        float v2 = el.z + er.z; v2 = v2 > 0.f ? v2 : 0.2f * v2;
        float v3 = el.w + er.w; v3 = v3 > 0.f ? v3 : 0.2f * v3;
        float M;
        M = fmaxf(m0, v0); z0 = z0 * __expf(m0 - M) + __expf(v0 - M); m0 = M;
        M = fmaxf(m1, v1); z1 = z1 * __expf(m1 - M) + __expf(v1 - M); m1 = M;
        M = fmaxf(m2, v2); z2 = z2 * __expf(m2 - M) + __expf(v2 - M); m2 = M;
        M = fmaxf(m3, v3); z3 = z3 * __expf(m3 - M) + __expf(v3 - M); m3 = M;
    }
    #pragma unroll
    for (int o = 16; o; o >>= 1) {
        float mo, zo, M;
        mo = __shfl_xor_sync(0xffffffffu, m0, o); zo = __shfl_xor_sync(0xffffffffu, z0, o);
        M = fmaxf(m0, mo); z0 = z0 * __expf(m0 - M) + zo * __expf(mo - M); m0 = M;
        mo = __shfl_xor_sync(0xffffffffu, m1, o); zo = __shfl_xor_sync(0xffffffffu, z1, o);
        M = fmaxf(m1, mo); z1 = z1 * __expf(m1 - M) + zo * __expf(mo - M); m1 = M;
        mo = __shfl_xor_sync(0xffffffffu, m2, o); zo = __shfl_xor_sync(0xffffffffu, z2, o);
        M = fmaxf(m2, mo); z2 = z2 * __expf(m2 - M) + zo * __expf(mo - M); m2 = M;
        mo = __shfl_xor_sync(0xffffffffu, m3, o); zo = __shfl_xor_sync(0xffffffffu, z3, o);
        M = fmaxf(m3, mo); z3 = z3 * __expf(m3 - M) + zo * __expf(mo - M); m3 = M;
    }
    if (lane == 0) {
        *(float4*)(g_m4 + n * 4) = make_float4(m0, m1, m2, m3);
        *(float4*)(g_iz4 + n * 4) = make_float4(
            1.f / fmaxf(z0, 1e-20f), 1.f / fmaxf(z1, 1e-20f),
            1.f / fmaxf(z2, 1e-20f), 1.f / fmaxf(z3, 1e-20f));
    }
}

// ---------------- pass B: weighted accumulate + residual + bias + leaky ----------------
__global__ __launch_bounds__(128) void k_agg(const float* __restrict__ bgat) {
    int n = blockIdx.x;
    int h = threadIdx.x >> 5, lane = threadIdx.x & 31;
    int beg = g_rowptr[n], end = g_rowptr[n + 1];
    float ern = g_er[n * 4 + h];
    float m   = g_m4[n * 4 + h];
    float iz  = g_iz4[n * 4 + h];

    float4 acc = make_float4(0.f, 0.f, 0.f, 0.f);
    int e = beg;
    for (; e + 4 <= end; e += 4) {
        int s0 = g_csrsrc[e + 0];
        int s1 = g_csrsrc[e + 1];
        int s2 = g_csrsrc[e + 2];
        int s3 = g_csrsrc[e + 3];
        float v0 = g_el[s0 * 4 + h] + ern;
        float v1 = g_el[s1 * 4 + h] + ern;
        float v2 = g_el[s2 * 4 + h] + ern;
        float v3 = g_el[s3 * 4 + h] + ern;
        float4 f0 = *(const float4*)(g_feat + (size_t)s0 * HDd + h * Dd + lane * 4);
        float4 f1 = *(const float4*)(g_feat + (size_t)s1 * HDd + h * Dd + lane * 4);
        float4 f2 = *(const float4*)(g_feat + (size_t)s2 * HDd + h * Dd + lane * 4);
        float4 f3 = *(const float4*)(g_feat + (size_t)s3 * HDd + h * Dd + lane * 4);
        v0 = v0 > 0.f ? v0 : 0.2f * v0;
        v1 = v1 > 0.f ? v1 : 0.2f * v1;
        v2 = v2 > 0.f ? v2 : 0.2f * v2;
        v3 = v3 > 0.f ? v3 : 0.2f * v3;
        float w0 = __expf(v0 - m), w1 = __expf(v1 - m);
        float w2 = __expf(v2 - m), w3 = __expf(v3 - m);
        acc.x += w0 * f0.x + w1 * f1.x + w2 * f2.x + w3 * f3.x;
        acc.y += w0 * f0.y + w1 * f1.y + w2 * f2.y + w3 * f3.y;
        acc.z += w0 * f0.z + w1 * f1.z + w2 * f2.z + w3 * f3.z;
        acc.w += w0 * f0.w + w1 * f1.w + w2 * f2.w + w3 * f3.w;
    }
    for (; e < end; e++) {
        int s = g_csrsrc[e];
        float v = g_el[s * 4 + h] + ern;
        v = v > 0.f ? v : 0.2f * v;
        float w = __expf(v - m);
        float4 f = *(const float4*)(g_feat + (size_t)s * HDd + h * Dd + lane * 4);
        acc.x += w * f.x; acc.y += w * f.y; acc.z += w * f.z; acc.w += w * f.w;
    }

    float* rp = g_res + (size_t)n * HDd + h * Dd + lane * 4;
    float4 r = *(float4*)rp;
    float4 bg = *(const float4*)(bgat + h * Dd + lane * 4);
    float4 o;
    o.x = acc.x * iz + r.x + bg.x;
    o.y = acc.y * iz + r.y + bg.y;
    o.z = acc.z * iz + r.z + bg.z;
    o.w = acc.w * iz + r.w + bg.w;
    o.x = o.x > 0.f ? o.x : 0.01f * o.x;
    o.y = o.y > 0.f ? o.y : 0.01f * o.y;
    o.z = o.z > 0.f ? o.z : 0.01f * o.z;
    o.w = o.w > 0.f ? o.w : 0.01f * o.w;
    *(float4*)rp = o;
}

// ---------------- layernorm over D=128 (warp per row), + b_nrm folded in ----------------
__global__ __launch_bounds__(128) void k_ln(
    const float* __restrict__ y, const float* __restrict__ bn,
    const float* __restrict__ g, const float* __restrict__ b,
    float* __restrict__ out)
{
    int row = blockIdx.x * 4 + (threadIdx.x >> 5);
    int lane = threadIdx.x & 31;
    if (row >= Nn) return;
    float4 v = ((const float4*)(y + (size_t)row * Dd))[lane];
    float4 bv = ((const float4*)bn)[lane];
    v.x += bv.x; v.y += bv.y; v.z += bv.z; v.w += bv.w;
    float s = v.x + v.y + v.z + v.w;
    #pragma unroll
    for (int o = 16; o; o >>= 1) s += __shfl_xor_sync(0xffffffffu, s, o);
    float mu = s * (1.f / 128.f);
    float dx = v.x - mu, dy = v.y - mu, dz = v.z - mu, dw = v.w - mu;
    float q = dx * dx + dy * dy + dz * dz + dw * dw;
    #pragma unroll
    for (int o = 16; o; o >>= 1) q += __shfl_xor_sync(0xffffffffu, q, o);
    float rstd = rsqrtf(q * (1.f / 128.f) + 1e-5f);
    float4 gg = ((const float4*)g)[lane];
    float4 bb = ((const float4*)b)[lane];
    float4 o4;
    o4.x = dx * rstd * gg.x + bb.x;
    o4.y = dy * rstd * gg.y + bb.y;
    o4.z = dz * rstd * gg.z + bb.z;
    o4.w = dw * rstd * gg.w + bb.w;
    ((float4*)(out + (size_t)row * Dd))[lane] = o4;
}

// ---------------- launch ----------------
extern "C" void kernel_launch(void* const* d_in, const int* in_sizes, int n_in,
                              void* d_out, int out_size)
{
    const float* features = (const float*)d_in[0];
    const int*   src      = (const int*)  d_in[1];
    const int*   dst      = (const int*)  d_in[2];
    const float* W_fc     = (const float*)d_in[3];
    const float* attn_l   = (const float*)d_in[4];
    const float* attn_r   = (const float*)d_in[5];
    const float* W_res    = (const float*)d_in[6];
    const float* b_gat    = (const float*)d_in[7];
    const float* W_nrm    = (const float*)d_in[8];
    const float* b_nrm    = (const float*)d_in[9];
    const float* ln_g     = (const float*)d_in[10];
    const float* ln_b     = (const float*)d_in[11];
    float* out = (float*)d_out;

    float *feat, *res, *y, *xA, *xB;
    cudaGetSymbolAddress((void**)&feat, g_feat);
    cudaGetSymbolAddress((void**)&res,  g_res);
    cudaGetSymbolAddress((void**)&y,    g_y);
    cudaGetSymbolAddress((void**)&xA,   g_xA);
    cudaGetSymbolAddress((void**)&xB,   g_xB);

    // CSR: zero,count,scan first; fill deferred so the fused GEMM is launch #4
    // (the profiler captures the 4th launch).
    k_zero_deg<<<(Nn + 255) / 256, 256>>>();
    k_count<<<(Ee + 255) / 256, 256>>>(dst);
    k_scan<<<1, 1024>>>();

    const int gy = (Nn + 127) / 128;   // 391

    const float* xin = features;
    for (int l = 0; l < Ll; l++) {
        const float* Wf = W_fc  + (size_t)l * Dd * HDd;
        const float* Wr = W_res + (size_t)l * Dd * HDd;
        const float* Wn = W_nrm + (size_t)l * HDd * Dd;

        // fused: feat = xin@Wf ; res = xin@Wr (same A)
        dim3 g1(2 * (HDd / 128), gy);
        gemm_tc<<<g1, 256>>>(xin, Wf, Wr, feat, res, Nn, HDd, Dd, HDd / 128);

        if (l == 0) k_fill<<<(Ee + 255) / 256, 256>>>(src, dst);

        k_attn<<<Nn, 128>>>(feat, attn_l + l * Hh * Dd, attn_r + l * Hh * Dd);
        k_mz<<<(Nn + 3) / 4, 128>>>();
        k_agg<<<Nn, 128>>>(b_gat + l * HDd);

        dim3 g2(Dd / 128, gy);
        gemm_tc<<<g2, 256>>>(res, Wn, nullptr, y, nullptr, Nn, Dd, HDd, Dd / 128);

        float* xout = (l == Ll - 1) ? out : ((l & 1) ? xB : xA);
        k_ln<<<(Nn + 3) / 4, 128>>>(y, b_nrm + l * Dd, ln_g + l * Dd, ln_b + l * Dd, xout);
        xin = xout;
    }
}

// round 5
// speedup vs baseline: 1.0849x; 1.0849x over previous
#include <cuda_runtime.h>
#include <mma.h>
#include <cstdint>
using namespace nvcuda;

#define Nn 50000
#define Ee 800000
#define Hh 4
#define Dd 128
#define HDd 512
#define Ll 4
#define MPAD 50048   // 391 * 128, pads GEMM M-tiles so epilogue stores are unguarded

#define WSZ (Dd * HDd)          // 65536 per weight matrix
#define NWEIGHT (3 * Ll * WSZ)  // 786432
#define NFEAT (Nn * Dd)         // 6.4M

// ---------------- scratch (static device memory; no allocations) ----------------
__device__ __align__(16) float g_feat[(size_t)MPAD * HDd];
__device__ __align__(16) float g_res [(size_t)MPAD * HDd];
__device__ __align__(16) float g_el[Nn * Hh];
__device__ __align__(16) float g_er[Nn * Hh];
__device__ __align__(16) float g_m4 [Nn * Hh];
__device__ __align__(16) float g_iz4[Nn * Hh];
__device__ __align__(16) float g_y [(size_t)MPAD * Dd];
__device__ __align__(16) float g_xA[(size_t)Nn * Dd];
__device__ __align__(16) float g_xB[(size_t)Nn * Dd];
__device__ __align__(16) float g_x0[(size_t)Nn * Dd];     // tf32-rounded features
__device__ __align__(16) float g_wr[NWEIGHT];             // tf32-rounded weights
__device__ int g_deg[Nn];
__device__ int g_rowptr[Nn + 1];
__device__ int g_cursor[Nn];
__device__ int g_csrsrc[Ee];

__device__ __forceinline__ float tf32r(float x) { return wmma::__float_to_tf32(x); }

// ---------------- preamble: round weights+features to tf32, zero deg ----------------
__global__ void k_pre(const float* __restrict__ Wf, const float* __restrict__ Wr,
                      const float* __restrict__ Wn, const float* __restrict__ feats)
{
    int i = blockIdx.x * blockDim.x + threadIdx.x;
    if (i < NFEAT) g_x0[i] = tf32r(feats[i]);
    if (i < Ll * WSZ) {
        g_wr[i]              = tf32r(Wf[i]);
        g_wr[Ll * WSZ + i]   = tf32r(Wr[i]);
        g_wr[2 * Ll * WSZ + i] = tf32r(Wn[i]);
    }
    if (i < Nn) g_deg[i] = 0;
}

__global__ void k_count(const int* __restrict__ dst) {
    int i = blockIdx.x * blockDim.x + threadIdx.x;
    if (i < Ee) atomicAdd(&g_deg[dst[i]], 1);
}

// single-block exclusive scan over g_deg -> g_rowptr (+ cursor init fused)
__global__ void k_scan() {
    __shared__ int sh[1024];
    __shared__ int carry;
    int t = threadIdx.x;
    if (t == 0) { carry = 0; g_rowptr[0] = 0; }
    __syncthreads();
    for (int base = 0; base < Nn; base += 1024) {
        int i = base + t;
        int v = (i < Nn) ? g_deg[i] : 0;
        sh[t] = v;
        __syncthreads();
        #pragma unroll
        for (int off = 1; off < 1024; off <<= 1) {
            int tv = (t >= off) ? sh[t - off] : 0;
            __syncthreads();
            sh[t] += tv;
            __syncthreads();
        }
        int incl = sh[t];
        int c = carry;
        __syncthreads();
        if (i < Nn) {
            g_rowptr[i + 1] = c + incl;
            g_cursor[i] = c + incl - v;
        }
        if (t == 1023) carry = c + incl;
        __syncthreads();
    }
}

__global__ void k_fill(const int* __restrict__ src, const int* __restrict__ dst) {
    int i = blockIdx.x * blockDim.x + threadIdx.x;
    if (i < Ee) {
        int p = atomicAdd(&g_cursor[dst[i]], 1);
        g_csrsrc[p] = src[i];
    }
}

// ---------------- cp.async helper ----------------
__device__ __forceinline__ void cp16(uint32_t dst, const void* src, bool pred) {
    int sz = pred ? 16 : 0;
    asm volatile("cp.async.cg.shared.global [%0], [%1], 16, %2;\n"
                 :: "r"(dst), "l"(src), "r"(sz));
}

// ---------------- tf32 tensor-core GEMM, 4-stage cp.async, fused dual output ----------
// Inputs MUST already be tf32-rounded (no cvt in kernel). CTA 128x128, BK=8,
// 8 warps (2m x 4n), warp tile 64x32. Compile-time K. C padded to MPAD.
template<int K, int TPH>
__global__ __launch_bounds__(256) void gemm_tc(
    const float* __restrict__ A,
    const float* __restrict__ B0, const float* __restrict__ B1,
    float* __restrict__ C0, float* __restrict__ C1, int M)
{
    constexpr int NN = TPH * 128;   // logical N of each output
    __shared__ float As[4][128][12];   // [m][k] ld 12
    __shared__ float Bs[4][8][132];    // [k][n] ld 132

    const int tid = threadIdx.x;
    const int warp = tid >> 5;
    const int wm = warp & 1, wn = warp >> 1;
    const int row0 = blockIdx.y * 128;

    int bx = blockIdx.x;
    const float* B = B0;
    float* C = C0;
    if (bx >= TPH) { bx -= TPH; B = B1; C = C1; }
    const int col0 = bx * 128;

    wmma::fragment<wmma::accumulator, 16, 16, 8, float> acc[4][2];
    #pragma unroll
    for (int i = 0; i < 4; i++)
        #pragma unroll
        for (int j = 0; j < 2; j++)
            wmma::fill_fragment(acc[i][j], 0.0f);

    constexpr int KT = K >> 3;

    auto stage = [&](int buf, int k0) {
        {
            int r = tid >> 1, q = tid & 1;
            int gm = row0 + r;
            const float* srcp = A + (size_t)gm * K + k0 + q * 4;
            uint32_t d = (uint32_t)__cvta_generic_to_shared(&As[buf][r][q * 4]);
            cp16(d, srcp, gm < M);
        }
        {
            int r = tid >> 5, nq = tid & 31;
            const float* srcp = B + (size_t)(k0 + r) * NN + col0 + nq * 4;
            uint32_t d = (uint32_t)__cvta_generic_to_shared(&Bs[buf][r][nq * 4]);
            cp16(d, srcp, true);
        }
        asm volatile("cp.async.commit_group;");
    };

    stage(0, 0);
    stage(1, 8);
    stage(2, 16);

    #pragma unroll 4
    for (int kt = 0; kt < KT; kt++) {
        if (kt + 3 < KT) asm volatile("cp.async.wait_group 2;");
        else             asm volatile("cp.async.wait_group 0;");
        __syncthreads();

        int buf = kt & 3;
        wmma::fragment<wmma::matrix_a, 16, 16, 8, wmma::precision::tf32, wmma::row_major> a[4];
        wmma::fragment<wmma::matrix_b, 16, 16, 8, wmma::precision::tf32, wmma::row_major> b[2];
        #pragma unroll
        for (int i = 0; i < 4; i++)
            wmma::load_matrix_sync(a[i], &As[buf][wm * 64 + i * 16][0], 12);
        #pragma unroll
        for (int j = 0; j < 2; j++)
            wmma::load_matrix_sync(b[j], &Bs[buf][0][wn * 32 + j * 16], 132);
        #pragma unroll
        for (int i = 0; i < 4; i++)
            #pragma unroll
            for (int j = 0; j < 2; j++)
                wmma::mma_sync(acc[i][j], a[i], b[j], acc[i][j]);

        if (kt + 3 < KT) stage((kt + 3) & 3, (kt + 3) << 3);
    }

    #pragma unroll
    for (int i = 0; i < 4; i++)
        #pragma unroll
        for (int j = 0; j < 2; j++)
            wmma::store_matrix_sync(
                C + (size_t)(row0 + wm * 64 + i * 16) * NN + col0 + wn * 32 + j * 16,
                acc[i][j], NN, wmma::mem_row_major);
}

// ---------------- attention coefficients: el/er = feat . attn ----------------
__global__ __launch_bounds__(128) void k_attn(
    const float* __restrict__ feat,
    const float* __restrict__ al, const float* __restrict__ ar)
{
    int n = blockIdx.x;
    int h = threadIdx.x >> 5, lane = threadIdx.x & 31;
    float4 f = ((const float4*)(feat + (size_t)n * HDd + h * Dd))[lane];
    float4 a = ((const float4*)(al + h * Dd))[lane];
    float4 b = ((const float4*)(ar + h * Dd))[lane];
    float sl = f.x * a.x + f.y * a.y + f.z * a.z + f.w * a.w;
    float sr = f.x * b.x + f.y * b.y + f.z * b.z + f.w * b.w;
    #pragma unroll
    for (int o = 16; o; o >>= 1) {
        sl += __shfl_xor_sync(0xffffffffu, sl, o);
        sr += __shfl_xor_sync(0xffffffffu, sr, o);
    }
    if (lane == 0) {
        g_el[n * Hh + h] = sl;
        g_er[n * Hh + h] = sr;
    }
}

// ---------------- pass A: per-(node,head) softmax max & denominator ----------------
__global__ __launch_bounds__(128) void k_mz() {
    int n = blockIdx.x * 4 + (threadIdx.x >> 5);
    int lane = threadIdx.x & 31;
    if (n >= Nn) return;
    int beg = g_rowptr[n], end = g_rowptr[n + 1];
    float4 er = *(const float4*)(g_er + n * 4);

    float m0 = -1e30f, m1 = -1e30f, m2 = -1e30f, m3 = -1e30f;
    float z0 = 0.f, z1 = 0.f, z2 = 0.f, z3 = 0.f;

    for (int e = beg + lane; e < end; e += 32) {
        int s = g_csrsrc[e];
        float4 el = *(const float4*)(g_el + s * 4);
        float v0 = el.x + er.x; v0 = v0 > 0.f ? v0 : 0.2f * v0;
        float v1 = el.y + er.y; v1 = v1 > 0.f ? v1 : 0.2f * v1;
        float v2 = el.z + er.z; v2 = v2 > 0.f ? v2 : 0.2f * v2;
        float v3 = el.w + er.w; v3 = v3 > 0.f ? v3 : 0.2f * v3;
        float M;
        M = fmaxf(m0, v0); z0 = z0 * __expf(m0 - M) + __expf(v0 - M); m0 = M;
        M = fmaxf(m1, v1); z1 = z1 * __expf(m1 - M) + __expf(v1 - M); m1 = M;
        M = fmaxf(m2, v2); z2 = z2 * __expf(m2 - M) + __expf(v2 - M); m2 = M;
        M = fmaxf(m3, v3); z3 = z3 * __expf(m3 - M) + __expf(v3 - M); m3 = M;
    }
    #pragma unroll
    for (int o = 16; o; o >>= 1) {
        float mo, zo, M;
        mo = __shfl_xor_sync(0xffffffffu, m0, o); zo = __shfl_xor_sync(0xffffffffu, z0, o);
        M = fmaxf(m0, mo); z0 = z0 * __expf(m0 - M) + zo * __expf(mo - M); m0 = M;
        mo = __shfl_xor_sync(0xffffffffu, m1, o); zo = __shfl_xor_sync(0xffffffffu, z1, o);
        M = fmaxf(m1, mo); z1 = z1 * __expf(m1 - M) + zo * __expf(mo - M); m1 = M;
        mo = __shfl_xor_sync(0xffffffffu, m2, o); zo = __shfl_xor_sync(0xffffffffu, z2, o);
        M = fmaxf(m2, mo); z2 = z2 * __expf(m2 - M) + zo * __expf(mo - M); m2 = M;
        mo = __shfl_xor_sync(0xffffffffu, m3, o); zo = __shfl_xor_sync(0xffffffffu, z3, o);
        M = fmaxf(m3, mo); z3 = z3 * __expf(m3 - M) + zo * __expf(mo - M); m3 = M;
    }
    if (lane == 0) {
        *(float4*)(g_m4 + n * 4) = make_float4(m0, m1, m2, m3);
        *(float4*)(g_iz4 + n * 4) = make_float4(
            1.f / fmaxf(z0, 1e-20f), 1.f / fmaxf(z1, 1e-20f),
            1.f / fmaxf(z2, 1e-20f), 1.f / fmaxf(z3, 1e-20f));
    }
}

// ---------------- pass B: weighted accumulate + residual + bias + leaky ------------
// output rounded to tf32 (feeds next GEMM only)
__global__ __launch_bounds__(128) void k_agg(const float* __restrict__ bgat) {
    int n = blockIdx.x;
    int h = threadIdx.x >> 5, lane = threadIdx.x & 31;
    int beg = g_rowptr[n], end = g_rowptr[n + 1];
    float ern = g_er[n * 4 + h];
    float m   = g_m4[n * 4 + h];
    float iz  = g_iz4[n * 4 + h];

    float4 acc = make_float4(0.f, 0.f, 0.f, 0.f);
    int e = beg;
    for (; e + 4 <= end; e += 4) {
        int s0 = g_csrsrc[e + 0];
        int s1 = g_csrsrc[e + 1];
        int s2 = g_csrsrc[e + 2];
        int s3 = g_csrsrc[e + 3];
        float v0 = g_el[s0 * 4 + h] + ern;
        float v1 = g_el[s1 * 4 + h] + ern;
        float v2 = g_el[s2 * 4 + h] + ern;
        float v3 = g_el[s3 * 4 + h] + ern;
        float4 f0 = *(const float4*)(g_feat + (size_t)s0 * HDd + h * Dd + lane * 4);
        float4 f1 = *(const float4*)(g_feat + (size_t)s1 * HDd + h * Dd + lane * 4);
        float4 f2 = *(const float4*)(g_feat + (size_t)s2 * HDd + h * Dd + lane * 4);
        float4 f3 = *(const float4*)(g_feat + (size_t)s3 * HDd + h * Dd + lane * 4);
        v0 = v0 > 0.f ? v0 : 0.2f * v0;
        v1 = v1 > 0.f ? v1 : 0.2f * v1;
        v2 = v2 > 0.f ? v2 : 0.2f * v2;
        v3 = v3 > 0.f ? v3 : 0.2f * v3;
        float w0 = __expf(v0 - m), w1 = __expf(v1 - m);
        float w2 = __expf(v2 - m), w3 = __expf(v3 - m);
        acc.x += w0 * f0.x + w1 * f1.x + w2 * f2.x + w3 * f3.x;
        acc.y += w0 * f0.y + w1 * f1.y + w2 * f2.y + w3 * f3.y;
        acc.z += w0 * f0.z + w1 * f1.z + w2 * f2.z + w3 * f3.z;
        acc.w += w0 * f0.w + w1 * f1.w + w2 * f2.w + w3 * f3.w;
    }
    for (; e < end; e++) {
        int s = g_csrsrc[e];
        float v = g_el[s * 4 + h] + ern;
        v = v > 0.f ? v : 0.2f * v;
        float w = __expf(v - m);
        float4 f = *(const float4*)(g_feat + (size_t)s * HDd + h * Dd + lane * 4);
        acc.x += w * f.x; acc.y += w * f.y; acc.z += w * f.z; acc.w += w * f.w;
    }

    float* rp = g_res + (size_t)n * HDd + h * Dd + lane * 4;
    float4 r = *(float4*)rp;
    float4 bg = *(const float4*)(bgat + h * Dd + lane * 4);
    float4 o;
    o.x = acc.x * iz + r.x + bg.x;
    o.y = acc.y * iz + r.y + bg.y;
    o.z = acc.z * iz + r.z + bg.z;
    o.w = acc.w * iz + r.w + bg.w;
    o.x = o.x > 0.f ? o.x : 0.01f * o.x;
    o.y = o.y > 0.f ? o.y : 0.01f * o.y;
    o.z = o.z > 0.f ? o.z : 0.01f * o.z;
    o.w = o.w > 0.f ? o.w : 0.01f * o.w;
    o.x = tf32r(o.x); o.y = tf32r(o.y); o.z = tf32r(o.z); o.w = tf32r(o.w);
    *(float4*)rp = o;
}

// ---------------- layernorm over D=128 (warp per row), + b_nrm folded in ----------
// doRound!=0 -> round output to tf32 (feeds next GEMM); final layer unrounded
__global__ __launch_bounds__(128) void k_ln(
    const float* __restrict__ y, const float* __restrict__ bn,
    const float* __restrict__ g, const float* __restrict__ b,
    float* __restrict__ out, int doRound)
{
    int row = blockIdx.x * 4 + (threadIdx.x >> 5);
    int lane = threadIdx.x & 31;
    if (row >= Nn) return;
    float4 v = ((const float4*)(y + (size_t)row * Dd))[lane];
    float4 bv = ((const float4*)bn)[lane];
    v.x += bv.x; v.y += bv.y; v.z += bv.z; v.w += bv.w;
    float s = v.x + v.y + v.z + v.w;
    #pragma unroll
    for (int o = 16; o; o >>= 1) s += __shfl_xor_sync(0xffffffffu, s, o);
    float mu = s * (1.f / 128.f);
    float dx = v.x - mu, dy = v.y - mu, dz = v.z - mu, dw = v.w - mu;
    float q = dx * dx + dy * dy + dz * dz + dw * dw;
    #pragma unroll
    for (int o = 16; o; o >>= 1) q += __shfl_xor_sync(0xffffffffu, q, o);
    float rstd = rsqrtf(q * (1.f / 128.f) + 1e-5f);
    float4 gg = ((const float4*)g)[lane];
    float4 bb = ((const float4*)b)[lane];
    float4 o4;
    o4.x = dx * rstd * gg.x + bb.x;
    o4.y = dy * rstd * gg.y + bb.y;
    o4.z = dz * rstd * gg.z + bb.z;
    o4.w = dw * rstd * gg.w + bb.w;
    if (doRound) {
        o4.x = tf32r(o4.x); o4.y = tf32r(o4.y);
        o4.z = tf32r(o4.z); o4.w = tf32r(o4.w);
    }
    ((float4*)(out + (size_t)row * Dd))[lane] = o4;
}

// ---------------- launch ----------------
extern "C" void kernel_launch(void* const* d_in, const int* in_sizes, int n_in,
                              void* d_out, int out_size)
{
    const float* features = (const float*)d_in[0];
    const int*   src      = (const int*)  d_in[1];
    const int*   dst      = (const int*)  d_in[2];
    const float* W_fc     = (const float*)d_in[3];
    const float* attn_l   = (const float*)d_in[4];
    const float* attn_r   = (const float*)d_in[5];
    const float* W_res    = (const float*)d_in[6];
    const float* b_gat    = (const float*)d_in[7];
    const float* W_nrm    = (const float*)d_in[8];
    const float* b_nrm    = (const float*)d_in[9];
    const float* ln_g     = (const float*)d_in[10];
    const float* ln_b     = (const float*)d_in[11];
    float* out = (float*)d_out;

    float *feat, *res, *y, *xA, *xB, *x0, *wr;
    cudaGetSymbolAddress((void**)&feat, g_feat);
    cudaGetSymbolAddress((void**)&res,  g_res);
    cudaGetSymbolAddress((void**)&y,    g_y);
    cudaGetSymbolAddress((void**)&xA,   g_xA);
    cudaGetSymbolAddress((void**)&xB,   g_xB);
    cudaGetSymbolAddress((void**)&x0,   g_x0);
    cudaGetSymbolAddress((void**)&wr,   g_wr);

    // preamble (rounding + zero), count, scan -> GEMM stays launch #4 for ncu
    k_pre<<<(NFEAT + 255) / 256, 256>>>(W_fc, W_res, W_nrm, features);
    k_count<<<(Ee + 255) / 256, 256>>>(dst);
    k_scan<<<1, 1024>>>();

    const int gy = (Nn + 127) / 128;   // 391

    const float* xin = x0;
    for (int l = 0; l < Ll; l++) {
        const float* Wf = wr + (size_t)l * WSZ;
        const float* Wr = wr + (size_t)(Ll + l) * WSZ;
        const float* Wn = wr + (size_t)(2 * Ll + l) * WSZ;

        // fused: feat = xin@Wf ; res = xin@Wr (same A), K=128, N=512 each
        dim3 g1(2 * (HDd / 128), gy);
        gemm_tc<Dd, HDd / 128><<<g1, 256>>>(xin, Wf, Wr, feat, res, Nn);

        if (l == 0) k_fill<<<(Ee + 255) / 256, 256>>>(src, dst);

        k_attn<<<Nn, 128>>>(feat, attn_l + l * Hh * Dd, attn_r + l * Hh * Dd);
        k_mz<<<(Nn + 3) / 4, 128>>>();
        k_agg<<<Nn, 128>>>(b_gat + l * HDd);

        // y = res @ Wn, K=512, N=128
        dim3 g2(Dd / 128, gy);
        gemm_tc<HDd, Dd / 128><<<g2, 256>>>(res, Wn, nullptr, y, nullptr, Nn);

        float* xout = (l == Ll - 1) ? out : ((l & 1) ? xB : xA);
        k_ln<<<(Nn + 3) / 4, 128>>>(y, b_nrm + l * Dd, ln_g + l * Dd, ln_b + l * Dd,
                                    xout, l != Ll - 1);
        xin = xout;
    }
}